// round 5
// baseline (speedup 1.0000x reference)
#include <cuda_runtime.h>
#include <cuda_bf16.h>
#include <cstdint>

#define TOK 49
#define HDIM 32
#define NH 8
#define NWIN 4096
#define MTOT (NWIN * TOK)   /* 200704 */
#define KDIM 256
#define NMASK 64
#define BMSTRIDE 2404

// ---------------- scratch (device globals: allocation-free) ----------------
__device__ float g_q[NWIN * NH * TOK * HDIM];   // [b,h,t,d]
__device__ float g_k[NWIN * NH * TOK * HDIM];
__device__ float g_v[NWIN * NH * TOK * HDIM];
__device__ float g_att[MTOT * KDIM];            // [b*49+t, h*32+d]
__device__ float g_bm[NMASK * NH * BMSTRIDE];   // fused bias+mask per (w,h)

__device__ __forceinline__ float4 ld4(const float* p) {
    return *reinterpret_cast<const float4*>(p);
}
__device__ __forceinline__ void st4(float* p, float4 v) {
    *reinterpret_cast<float4*>(p) = v;
}
__device__ __forceinline__ void st2(float* p, float2 v) {
    *reinterpret_cast<float2*>(p) = v;
}
__device__ __forceinline__ uint32_t f2tf(float f) {
    uint32_t u;
    asm("cvt.rna.tf32.f32 %0, %1;" : "=r"(u) : "f"(f));
    return u;
}
__device__ __forceinline__ void ld128(uint32_t r[4], const uint32_t* p) {
    uint4 v = *reinterpret_cast<const uint4*>(p);
    r[0] = v.x; r[1] = v.y; r[2] = v.z; r[3] = v.w;
}
__device__ __forceinline__ void mma_tf32(float c[4],
                                         uint32_t a0, uint32_t a1, uint32_t a2, uint32_t a3,
                                         uint32_t b0, uint32_t b1) {
    asm volatile(
        "mma.sync.aligned.m16n8k8.row.col.f32.tf32.tf32.f32 "
        "{%0,%1,%2,%3}, {%4,%5,%6,%7}, {%8,%9}, {%0,%1,%2,%3};"
        : "+f"(c[0]), "+f"(c[1]), "+f"(c[2]), "+f"(c[3])
        : "r"(a0), "r"(a1), "r"(a2), "r"(a3), "r"(b0), "r"(b1));
}

// ---------------------------------------------------------------------------
// tf32 tensor-core GEMM (NT): C[m,n] = sum_k A[m,k]*B[n,k] + bias[n]
// Block 128(m) x 256(n), BK=16, 256 threads = 8 warps (2m x 4n), warp tile
// 64x64. Fragment-major smem layout: every operand fetch is a conflict-free
// LDS.128 delivering a full mma fragment. Double-buffered, 1 sync per K-tile.
//
// A layout (per 16-k stage, word index, m in 0..127, k in 0..15):
//   mt=m>>4, g=m&7, half=(m>>3)&1, kb=k>>3, tig=k&3, kh=(k>>2)&1
//   W_A = 128*(mt+8*kb) + 4*(tig + 4*(g&1) + 8*(g>>1)) + (half + 2*kh)
// B layout (n in 0..255):
//   nt=n>>3, g=n&7
//   W_B = 2048*kb + 128*(nt>>1) + 4*(tig + 4*(g&1) + 8*(g>>1)) + (kh + 2*(nt&1))
// ---------------------------------------------------------------------------
template <int MODE>
__global__ __launch_bounds__(256, 1)
void gemm_tf32(const float* __restrict__ Ain, const float* __restrict__ B,
               const float* __restrict__ bias, float* __restrict__ C, int N)
{
    const float* A = (MODE == 1) ? (const float*)g_att : Ain;

    __shared__ uint32_t As[2 * 2048];
    __shared__ uint32_t Bs[2 * 4096];

    const int tid  = threadIdx.x;
    const int m0   = blockIdx.x * 128;
    const int n0   = blockIdx.y * 256;
    const int warp = tid >> 5;
    const int lane = tid & 31;
    const int g    = lane >> 2;
    const int tig  = lane & 3;
    const int wm   = warp & 1;        // 0..1  (m)
    const int wn   = warp >> 1;       // 0..3  (n)
    const int lp   = 4 * (tig + 4 * (g & 1) + 8 * (g >> 1));

    // A loader: row ra, k = kc0..kc0+7  (kb fixed = tid&1)
    const int ra   = tid >> 1;
    const int kc0  = (tid & 1) * 8;
    const int ga   = ra & 7;
    const int baseA = 128 * ((ra >> 4) + 8 * (tid & 1))
                    + 16 * (ga & 1) + 32 * (ga >> 1) + ((ra >> 3) & 1);
    const float* Ap = A + (size_t)(m0 + ra) * KDIM + kc0;

    // B loader: row tid, k = 0..15
    const int gb   = tid & 7;
    const int baseB = 128 * (tid >> 4) + 16 * (gb & 1) + 32 * (gb >> 1)
                    + 2 * ((tid >> 3) & 1);
    const float* Bp = B + (size_t)(n0 + tid) * KDIM;

    float acc[4][8][4];
#pragma unroll
    for (int mi = 0; mi < 4; mi++)
#pragma unroll
        for (int ni = 0; ni < 8; ni++)
#pragma unroll
            for (int e = 0; e < 4; e++) acc[mi][ni][e] = 0.f;

    float4 pa0 = ld4(Ap), pa1 = ld4(Ap + 4);
    float4 pb0 = ld4(Bp), pb1 = ld4(Bp + 4), pb2 = ld4(Bp + 8), pb3 = ld4(Bp + 12);

    // store prefetched regs (tf32-rounded) into stage s
    auto store_stage = [&](int s) {
        uint32_t* wa = As + s * 2048 + baseA;
        wa[0]  = f2tf(pa0.x); wa[4]  = f2tf(pa0.y);
        wa[8]  = f2tf(pa0.z); wa[12] = f2tf(pa0.w);
        wa[2]  = f2tf(pa1.x); wa[6]  = f2tf(pa1.y);
        wa[10] = f2tf(pa1.z); wa[14] = f2tf(pa1.w);
        uint32_t* wb = Bs + s * 4096 + baseB;
        wb[0]  = f2tf(pb0.x); wb[4]  = f2tf(pb0.y);
        wb[8]  = f2tf(pb0.z); wb[12] = f2tf(pb0.w);
        wb[1]  = f2tf(pb1.x); wb[5]  = f2tf(pb1.y);
        wb[9]  = f2tf(pb1.z); wb[13] = f2tf(pb1.w);
        wb[2048] = f2tf(pb2.x); wb[2052] = f2tf(pb2.y);
        wb[2056] = f2tf(pb2.z); wb[2060] = f2tf(pb2.w);
        wb[2049] = f2tf(pb3.x); wb[2053] = f2tf(pb3.y);
        wb[2057] = f2tf(pb3.z); wb[2061] = f2tf(pb3.w);
    };

    store_stage(0);
    __syncthreads();
    int s = 0;

#pragma unroll 1
    for (int iter = 0; iter < KDIM / 16; iter++) {
        if (iter < KDIM / 16 - 1) {
            Ap += 16; Bp += 16;
            pa0 = ld4(Ap); pa1 = ld4(Ap + 4);
            pb0 = ld4(Bp); pb1 = ld4(Bp + 4); pb2 = ld4(Bp + 8); pb3 = ld4(Bp + 12);
        }
        const uint32_t* sA = As + s * 2048;
        const uint32_t* sB = Bs + s * 4096;
#pragma unroll
        for (int kb = 0; kb < 2; kb++) {
            uint32_t a[4][4], bf[4][4];
#pragma unroll
            for (int mi = 0; mi < 4; mi++)
                ld128(a[mi], sA + 128 * (wm * 4 + mi + 8 * kb) + lp);
#pragma unroll
            for (int j = 0; j < 4; j++)
                ld128(bf[j], sB + 2048 * kb + 128 * (wn * 4 + j) + lp);
#pragma unroll
            for (int mi = 0; mi < 4; mi++)
#pragma unroll
                for (int j = 0; j < 4; j++) {
                    mma_tf32(acc[mi][2 * j],     a[mi][0], a[mi][1], a[mi][2], a[mi][3],
                             bf[j][0], bf[j][1]);
                    mma_tf32(acc[mi][2 * j + 1], a[mi][0], a[mi][1], a[mi][2], a[mi][3],
                             bf[j][2], bf[j][3]);
                }
        }
        if (iter < KDIM / 16 - 1) {
            s ^= 1;
            store_stage(s);
            __syncthreads();
        }
    }

    // epilogue
    if (MODE == 0) {
        const float SC = 0.17677669529663687f;
#pragma unroll
        for (int mi = 0; mi < 4; mi++) {
#pragma unroll
            for (int half = 0; half < 2; half++) {
                const int m  = m0 + wm * 64 + mi * 16 + g + half * 8;
                const int bw = m / TOK;
                const int t  = m - bw * TOK;
#pragma unroll
                for (int ni = 0; ni < 8; ni++) {
                    const int n     = n0 + wn * 64 + ni * 8 + 2 * tig;
                    const int which = n >> 8;
                    const int h     = (n >> 5) & 7;
                    const int d     = n & 31;
                    float2 v;
                    v.x = acc[mi][ni][half * 2 + 0] + bias[n + 0];
                    v.y = acc[mi][ni][half * 2 + 1] + bias[n + 1];
                    if (which == 0) { v.x *= SC; v.y *= SC; }
                    float* dst = (which == 0) ? g_q : (which == 1) ? g_k : g_v;
                    st2(&dst[(size_t)((bw * NH + h) * TOK + t) * HDIM + d], v);
                }
            }
        }
    } else {
#pragma unroll
        for (int mi = 0; mi < 4; mi++) {
#pragma unroll
            for (int half = 0; half < 2; half++) {
                const int m = m0 + wm * 64 + mi * 16 + g + half * 8;
#pragma unroll
                for (int ni = 0; ni < 8; ni++) {
                    const int n = n0 + wn * 64 + ni * 8 + 2 * tig;
                    float2 v;
                    v.x = acc[mi][ni][half * 2 + 0] + bias[n + 0];
                    v.y = acc[mi][ni][half * 2 + 1] + bias[n + 1];
                    st2(C + (size_t)m * N + n, v);
                }
            }
        }
    }
}

// ---------------------------------------------------------------------------
// Precompute fused bias+mask
// ---------------------------------------------------------------------------
__global__ void bm_precompute(const float* __restrict__ bias_table,
                              const int* __restrict__ rel_index,
                              const float* __restrict__ mask)
{
    const int w = blockIdx.x >> 3;
    float* dst = g_bm + (size_t)blockIdx.x * BMSTRIDE;
    const int h = blockIdx.x & 7;
    const float* mrow = mask + (size_t)w * (TOK * TOK);
    for (int e = threadIdx.x; e < TOK * TOK; e += 256)
        dst[e] = bias_table[rel_index[e] * NH + h] + mrow[e];
}

// ---------------------------------------------------------------------------
// Warp-synchronous attention (unchanged from round 4 — known good)
// ---------------------------------------------------------------------------
#define QS 36
#define PS 56

__global__ __launch_bounds__(256)
void attn_kernel()
{
    __shared__ float sq[TOK * QS];
    __shared__ float sk[TOK * QS];
    __shared__ float sv[56 * QS];
    __shared__ float sp[TOK * PS];

    const int tid  = threadIdx.x;
    const int warp = tid >> 5;
    const int lane = tid & 31;
    const int bh   = blockIdx.x;
    const int b    = bh >> 3;
    const int h    = bh & 7;
    const int base = bh * (TOK * HDIM);

    for (int idx = tid; idx < 56 * 8; idx += 256) {
        const int r = idx >> 3;
        const int c = (idx & 7) * 4;
        if (r < TOK) {
            st4(&sq[r * QS + c], ld4(g_q + base + r * HDIM + c));
            st4(&sk[r * QS + c], ld4(g_k + base + r * HDIM + c));
            st4(&sv[r * QS + c], ld4(g_v + base + r * HDIM + c));
        } else {
            st4(&sv[r * QS + c], make_float4(0.f, 0.f, 0.f, 0.f));
        }
    }
    __syncthreads();

    const int r0 = (warp == 7) ? 42 : warp * 6;

    float acc0[7], acc1[7];
#pragma unroll
    for (int ii = 0; ii < 7; ii++) { acc0[ii] = 0.f; acc1[ii] = 0.f; }

    const bool hi = (lane < 17);
    const int klo = lane * QS;
    const int khi = (hi ? (lane + 32) : lane) * QS;

#pragma unroll
    for (int dc = 0; dc < 32; dc += 8) {
        float4 k0a = ld4(&sk[klo + dc]);
        float4 k0b = ld4(&sk[klo + dc + 4]);
        float4 k1a = ld4(&sk[khi + dc]);
        float4 k1b = ld4(&sk[khi + dc + 4]);
#pragma unroll
        for (int ii = 0; ii < 7; ii++) {
            const int i = r0 + ii;
            const float4 qa = ld4(&sq[i * QS + dc]);
            const float4 qb = ld4(&sq[i * QS + dc + 4]);
            float a0 = acc0[ii], a1 = acc1[ii];
            a0 = fmaf(qa.x, k0a.x, a0); a1 = fmaf(qa.x, k1a.x, a1);
            a0 = fmaf(qa.y, k0a.y, a0); a1 = fmaf(qa.y, k1a.y, a1);
            a0 = fmaf(qa.z, k0a.z, a0); a1 = fmaf(qa.z, k1a.z, a1);
            a0 = fmaf(qa.w, k0a.w, a0); a1 = fmaf(qa.w, k1a.w, a1);
            a0 = fmaf(qb.x, k0b.x, a0); a1 = fmaf(qb.x, k1b.x, a1);
            a0 = fmaf(qb.y, k0b.y, a0); a1 = fmaf(qb.y, k1b.y, a1);
            a0 = fmaf(qb.z, k0b.z, a0); a1 = fmaf(qb.z, k1b.z, a1);
            a0 = fmaf(qb.w, k0b.w, a0); a1 = fmaf(qb.w, k1b.w, a1);
            acc0[ii] = a0; acc1[ii] = a1;
        }
    }

    const float* bm = g_bm + (size_t)(((b & (NMASK - 1)) << 3) + h) * BMSTRIDE;
#pragma unroll
    for (int ii = 0; ii < 7; ii++) {
        const int i = r0 + ii;
        float x0 = acc0[ii] + bm[i * TOK + lane];
        float x1 = hi ? (acc1[ii] + bm[i * TOK + 32 + lane]) : -1e30f;
        float mx = fmaxf(x0, x1);
#pragma unroll
        for (int off = 16; off > 0; off >>= 1)
            mx = fmaxf(mx, __shfl_xor_sync(0xffffffffu, mx, off));
        float e0 = __expf(x0 - mx);
        float e1 = hi ? __expf(x1 - mx) : 0.f;
        float s = e0 + e1;
#pragma unroll
        for (int off = 16; off > 0; off >>= 1)
            s += __shfl_xor_sync(0xffffffffu, s, off);
        const float inv = 1.f / s;
        sp[i * PS + lane] = e0 * inv;
        if (lane < 24)
            sp[i * PS + 32 + lane] = hi ? e1 * inv : 0.f;
    }
    __syncwarp();

    float o[7];
#pragma unroll
    for (int ii = 0; ii < 7; ii++) o[ii] = 0.f;

#pragma unroll
    for (int jc = 0; jc < 56; jc += 8) {
        float v8[8];
#pragma unroll
        for (int jj = 0; jj < 8; jj++) v8[jj] = sv[(jc + jj) * QS + lane];
#pragma unroll
        for (int ii = 0; ii < 7; ii++) {
            const int i = r0 + ii;
            const float4 p0 = ld4(&sp[i * PS + jc]);
            const float4 p1 = ld4(&sp[i * PS + jc + 4]);
            float a = o[ii];
            a = fmaf(p0.x, v8[0], a);
            a = fmaf(p0.y, v8[1], a);
            a = fmaf(p0.z, v8[2], a);
            a = fmaf(p0.w, v8[3], a);
            a = fmaf(p1.x, v8[4], a);
            a = fmaf(p1.y, v8[5], a);
            a = fmaf(p1.z, v8[6], a);
            a = fmaf(p1.w, v8[7], a);
            o[ii] = a;
        }
    }

#pragma unroll
    for (int ii = 0; ii < 7; ii++) {
        const int i = r0 + ii;
        g_att[(size_t)(b * TOK + i) * KDIM + h * HDIM + lane] = o[ii];
    }
}

// ---------------------------------------------------------------------------
extern "C" void kernel_launch(void* const* d_in, const int* in_sizes, int n_in,
                              void* d_out, int out_size)
{
    const float* x          = (const float*)d_in[0];
    const float* mask       = (const float*)d_in[1];
    const float* qkv_w      = (const float*)d_in[2];
    const float* qkv_b      = (const float*)d_in[3];
    const float* proj_w     = (const float*)d_in[4];
    const float* proj_b     = (const float*)d_in[5];
    const float* bias_table = (const float*)d_in[6];
    const int*   rel_index  = (const int*)d_in[7];
    float*       out        = (float*)d_out;

    bm_precompute<<<NMASK * NH, 256>>>(bias_table, rel_index, mask);

    dim3 g1(MTOT / 128, 768 / 256);
    gemm_tf32<0><<<g1, 256>>>(x, qkv_w, qkv_b, nullptr, 768);

    attn_kernel<<<NWIN * NH, 256>>>();

    dim3 g2(MTOT / 128, KDIM / 256);
    gemm_tf32<1><<<g2, 256>>>(nullptr, proj_w, proj_b, out, KDIM);
}

// round 7
// speedup vs baseline: 1.3470x; 1.3470x over previous
#include <cuda_runtime.h>
#include <cuda_bf16.h>
#include <cstdint>

#define TOK 49
#define HDIM 32
#define NH 8
#define NWIN 4096
#define MTOT (NWIN * TOK)   /* 200704 */
#define KDIM 256
#define NMASK 64
#define BMSTRIDE 2404

// ---------------- scratch (device globals: allocation-free) ----------------
__device__ float g_q[NWIN * NH * TOK * HDIM];   // [b,h,t,d]
__device__ float g_k[NWIN * NH * TOK * HDIM];
__device__ float g_v[NWIN * NH * TOK * HDIM];
__device__ float g_att[MTOT * KDIM];            // [b*49+t, h*32+d] (tf32-rounded)
__device__ float g_bm[NMASK * NH * BMSTRIDE];   // fused bias+mask per (w,h)
__device__ float g_xr[MTOT * KDIM];             // x, tf32-rounded
__device__ float g_wq[768 * KDIM];              // qkv_w, tf32-rounded
__device__ float g_wp[KDIM * KDIM];             // proj_w, tf32-rounded

__device__ __forceinline__ float4 ld4(const float* p) {
    return *reinterpret_cast<const float4*>(p);
}
__device__ __forceinline__ void st4(float* p, float4 v) {
    *reinterpret_cast<float4*>(p) = v;
}
__device__ __forceinline__ void st2(float* p, float2 v) {
    *reinterpret_cast<float2*>(p) = v;
}
__device__ __forceinline__ uint32_t f2tf(float f) {
    uint32_t u;
    asm("cvt.rna.tf32.f32 %0, %1;" : "=r"(u) : "f"(f));
    return u;
}
__device__ __forceinline__ void cp16(float* smem_dst, const float* gmem_src) {
    uint32_t s = (uint32_t)__cvta_generic_to_shared(smem_dst);
    asm volatile("cp.async.cg.shared.global [%0], [%1], 16;" :: "r"(s), "l"(gmem_src));
}
__device__ __forceinline__ void mma_tf32(float c[4],
                                         uint32_t a0, uint32_t a1, uint32_t a2, uint32_t a3,
                                         uint32_t b0, uint32_t b1) {
    asm volatile(
        "mma.sync.aligned.m16n8k8.row.col.f32.tf32.tf32.f32 "
        "{%0,%1,%2,%3}, {%4,%5,%6,%7}, {%8,%9}, {%0,%1,%2,%3};"
        : "+f"(c[0]), "+f"(c[1]), "+f"(c[2]), "+f"(c[3])
        : "r"(a0), "r"(a1), "r"(a2), "r"(a3), "r"(b0), "r"(b1));
}

// ---------------------------------------------------------------------------
// elementwise tf32 (rna) pre-round
// ---------------------------------------------------------------------------
__global__ void round4(const float* __restrict__ in, float* __restrict__ out) {
    const size_t i = (size_t)(blockIdx.x * blockDim.x + threadIdx.x) * 4;
    float4 v = ld4(in + i);
    v.x = __uint_as_float(f2tf(v.x));
    v.y = __uint_as_float(f2tf(v.y));
    v.z = __uint_as_float(f2tf(v.z));
    v.w = __uint_as_float(f2tf(v.w));
    st4(out + i, v);
}

// ---------------------------------------------------------------------------
// tf32 tensor-core GEMM (NT): C[m,n] = sum_k A[m,k]*B[n,k] + bias[n]
// Block 128x128, BK=16, 256 threads = 8 warps (2m x 4n), warp tile 64x32.
// Inputs pre-rounded to tf32. cp.async double-buffered: copy(i+1) overlaps
// compute(i). Smem rows stride 20 floats -> conflict-free scalar LDS.
// MODE 0: epilogue scatters into g_q/g_k/g_v (q scaled). MODE 1: plain.
// ---------------------------------------------------------------------------
#define RS 20   // smem row stride (floats)

template <int MODE>
__global__ __launch_bounds__(256, 2)
void gemm_tf32(const float* __restrict__ A, const float* __restrict__ B,
               const float* __restrict__ bias, float* __restrict__ C, int N)
{
    __shared__ float As[2][128 * RS];
    __shared__ float Bs[2][128 * RS];

    const int tid  = threadIdx.x;
    const int m0   = blockIdx.x * 128;
    const int n0   = blockIdx.y * 128;
    const int warp = tid >> 5;
    const int lane = tid & 31;
    const int g    = lane >> 2;
    const int tig  = lane & 3;
    const int wm   = warp & 1;
    const int wn   = warp >> 1;

    // loader: row = tid>>1, two 16B chunks at float offset (tid&1)*8
    const int lr = tid >> 1;
    const int lc = (tid & 1) * 8;
    const float* Ag = A + (size_t)(m0 + lr) * KDIM + lc;
    const float* Bg = B + (size_t)(n0 + lr) * KDIM + lc;
    const int sdst = lr * RS + lc;

    float acc[4][4][4];
#pragma unroll
    for (int mi = 0; mi < 4; mi++)
#pragma unroll
        for (int ni = 0; ni < 4; ni++)
#pragma unroll
            for (int e = 0; e < 4; e++) acc[mi][ni][e] = 0.f;

    auto issue = [&](int s, int kt) {
        cp16(&As[s][sdst],     Ag + kt);
        cp16(&As[s][sdst + 4], Ag + kt + 4);
        cp16(&Bs[s][sdst],     Bg + kt);
        cp16(&Bs[s][sdst + 4], Bg + kt + 4);
        asm volatile("cp.async.commit_group;");
    };

    issue(0, 0);

    const int NT = KDIM / 16;
#pragma unroll 1
    for (int iter = 0; iter < NT; iter++) {
        asm volatile("cp.async.wait_group 0;");
        __syncthreads();
        if (iter + 1 < NT) issue((iter + 1) & 1, (iter + 1) * 16);

        const uint32_t* sA = reinterpret_cast<const uint32_t*>(As[iter & 1]);
        const uint32_t* sB = reinterpret_cast<const uint32_t*>(Bs[iter & 1]);
#pragma unroll
        for (int k8 = 0; k8 < 16; k8 += 8) {
            uint32_t a[4][4], bf[4][2];
#pragma unroll
            for (int mi = 0; mi < 4; mi++) {
                const int mg = (wm * 64 + mi * 16 + g) * RS;
                a[mi][0] = sA[mg + k8 + tig];
                a[mi][1] = sA[mg + 8 * RS + k8 + tig];
                a[mi][2] = sA[mg + k8 + tig + 4];
                a[mi][3] = sA[mg + 8 * RS + k8 + tig + 4];
            }
#pragma unroll
            for (int ni = 0; ni < 4; ni++) {
                const int ng = (wn * 32 + ni * 8 + g) * RS;
                bf[ni][0] = sB[ng + k8 + tig];
                bf[ni][1] = sB[ng + k8 + tig + 4];
            }
#pragma unroll
            for (int mi = 0; mi < 4; mi++)
#pragma unroll
                for (int ni = 0; ni < 4; ni++)
                    mma_tf32(acc[mi][ni], a[mi][0], a[mi][1], a[mi][2], a[mi][3],
                             bf[ni][0], bf[ni][1]);
        }
        __syncthreads();
    }

    // epilogue: c0/c1 -> (row g, cols 2*tig..+1), c2/c3 -> (row g+8)
    if (MODE == 0) {
        const float SC = 0.17677669529663687f;
#pragma unroll
        for (int mi = 0; mi < 4; mi++) {
#pragma unroll
            for (int half = 0; half < 2; half++) {
                const int m  = m0 + wm * 64 + mi * 16 + g + half * 8;
                const int bw = m / TOK;
                const int t  = m - bw * TOK;
#pragma unroll
                for (int ni = 0; ni < 4; ni++) {
                    const int n     = n0 + wn * 32 + ni * 8 + 2 * tig;
                    const int which = n >> 8;
                    const int h     = (n >> 5) & 7;
                    const int d     = n & 31;
                    float2 v;
                    v.x = acc[mi][ni][half * 2 + 0] + bias[n + 0];
                    v.y = acc[mi][ni][half * 2 + 1] + bias[n + 1];
                    if (which == 0) { v.x *= SC; v.y *= SC; }
                    float* dst = (which == 0) ? g_q : (which == 1) ? g_k : g_v;
                    st2(&dst[(size_t)((bw * NH + h) * TOK + t) * HDIM + d], v);
                }
            }
        }
    } else {
#pragma unroll
        for (int mi = 0; mi < 4; mi++) {
#pragma unroll
            for (int half = 0; half < 2; half++) {
                const int m = m0 + wm * 64 + mi * 16 + g + half * 8;
#pragma unroll
                for (int ni = 0; ni < 4; ni++) {
                    const int n = n0 + wn * 32 + ni * 8 + 2 * tig;
                    float2 v;
                    v.x = acc[mi][ni][half * 2 + 0] + bias[n + 0];
                    v.y = acc[mi][ni][half * 2 + 1] + bias[n + 1];
                    st2(C + (size_t)m * N + n, v);
                }
            }
        }
    }
}

// ---------------------------------------------------------------------------
// Precompute fused bias+mask
// ---------------------------------------------------------------------------
__global__ void bm_precompute(const float* __restrict__ bias_table,
                              const int* __restrict__ rel_index,
                              const float* __restrict__ mask)
{
    const int w = blockIdx.x >> 3;
    float* dst = g_bm + (size_t)blockIdx.x * BMSTRIDE;
    const int h = blockIdx.x & 7;
    const float* mrow = mask + (size_t)w * (TOK * TOK);
    for (int e = threadIdx.x; e < TOK * TOK; e += 256)
        dst[e] = bias_table[rel_index[e] * NH + h] + mrow[e];
}

// ---------------------------------------------------------------------------
// Warp-synchronous attention (R4 structure; output tf32-rounded for proj GEMM)
// ---------------------------------------------------------------------------
#define QS 36
#define PS 56

__global__ __launch_bounds__(256)
void attn_kernel()
{
    __shared__ float sq[TOK * QS];
    __shared__ float sk[TOK * QS];
    __shared__ float sv[56 * QS];
    __shared__ float sp[TOK * PS];

    const int tid  = threadIdx.x;
    const int warp = tid >> 5;
    const int lane = tid & 31;
    const int bh   = blockIdx.x;
    const int b    = bh >> 3;
    const int h    = bh & 7;
    const int base = bh * (TOK * HDIM);

    for (int idx = tid; idx < 56 * 8; idx += 256) {
        const int r = idx >> 3;
        const int c = (idx & 7) * 4;
        if (r < TOK) {
            st4(&sq[r * QS + c], ld4(g_q + base + r * HDIM + c));
            st4(&sk[r * QS + c], ld4(g_k + base + r * HDIM + c));
            st4(&sv[r * QS + c], ld4(g_v + base + r * HDIM + c));
        } else {
            st4(&sv[r * QS + c], make_float4(0.f, 0.f, 0.f, 0.f));
        }
    }
    __syncthreads();

    const int r0 = (warp == 7) ? 42 : warp * 6;

    float acc0[7], acc1[7];
#pragma unroll
    for (int ii = 0; ii < 7; ii++) { acc0[ii] = 0.f; acc1[ii] = 0.f; }

    const bool hi = (lane < 17);
    const int klo = lane * QS;
    const int khi = (hi ? (lane + 32) : lane) * QS;

#pragma unroll
    for (int dc = 0; dc < 32; dc += 8) {
        float4 k0a = ld4(&sk[klo + dc]);
        float4 k0b = ld4(&sk[klo + dc + 4]);
        float4 k1a = ld4(&sk[khi + dc]);
        float4 k1b = ld4(&sk[khi + dc + 4]);
#pragma unroll
        for (int ii = 0; ii < 7; ii++) {
            const int i = r0 + ii;
            const float4 qa = ld4(&sq[i * QS + dc]);
            const float4 qb = ld4(&sq[i * QS + dc + 4]);
            float a0 = acc0[ii], a1 = acc1[ii];
            a0 = fmaf(qa.x, k0a.x, a0); a1 = fmaf(qa.x, k1a.x, a1);
            a0 = fmaf(qa.y, k0a.y, a0); a1 = fmaf(qa.y, k1a.y, a1);
            a0 = fmaf(qa.z, k0a.z, a0); a1 = fmaf(qa.z, k1a.z, a1);
            a0 = fmaf(qa.w, k0a.w, a0); a1 = fmaf(qa.w, k1a.w, a1);
            a0 = fmaf(qb.x, k0b.x, a0); a1 = fmaf(qb.x, k1b.x, a1);
            a0 = fmaf(qb.y, k0b.y, a0); a1 = fmaf(qb.y, k1b.y, a1);
            a0 = fmaf(qb.z, k0b.z, a0); a1 = fmaf(qb.z, k1b.z, a1);
            a0 = fmaf(qb.w, k0b.w, a0); a1 = fmaf(qb.w, k1b.w, a1);
            acc0[ii] = a0; acc1[ii] = a1;
        }
    }

    const float* bm = g_bm + (size_t)(((b & (NMASK - 1)) << 3) + h) * BMSTRIDE;
#pragma unroll
    for (int ii = 0; ii < 7; ii++) {
        const int i = r0 + ii;
        float x0 = acc0[ii] + bm[i * TOK + lane];
        float x1 = hi ? (acc1[ii] + bm[i * TOK + 32 + lane]) : -1e30f;
        float mx = fmaxf(x0, x1);
#pragma unroll
        for (int off = 16; off > 0; off >>= 1)
            mx = fmaxf(mx, __shfl_xor_sync(0xffffffffu, mx, off));
        float e0 = __expf(x0 - mx);
        float e1 = hi ? __expf(x1 - mx) : 0.f;
        float s = e0 + e1;
#pragma unroll
        for (int off = 16; off > 0; off >>= 1)
            s += __shfl_xor_sync(0xffffffffu, s, off);
        const float inv = 1.f / s;
        sp[i * PS + lane] = e0 * inv;
        if (lane < 24)
            sp[i * PS + 32 + lane] = hi ? e1 * inv : 0.f;
    }
    __syncwarp();

    float o[7];
#pragma unroll
    for (int ii = 0; ii < 7; ii++) o[ii] = 0.f;

#pragma unroll
    for (int jc = 0; jc < 56; jc += 8) {
        float v8[8];
#pragma unroll
        for (int jj = 0; jj < 8; jj++) v8[jj] = sv[(jc + jj) * QS + lane];
#pragma unroll
        for (int ii = 0; ii < 7; ii++) {
            const int i = r0 + ii;
            const float4 p0 = ld4(&sp[i * PS + jc]);
            const float4 p1 = ld4(&sp[i * PS + jc + 4]);
            float a = o[ii];
            a = fmaf(p0.x, v8[0], a);
            a = fmaf(p0.y, v8[1], a);
            a = fmaf(p0.z, v8[2], a);
            a = fmaf(p0.w, v8[3], a);
            a = fmaf(p1.x, v8[4], a);
            a = fmaf(p1.y, v8[5], a);
            a = fmaf(p1.z, v8[6], a);
            a = fmaf(p1.w, v8[7], a);
            o[ii] = a;
        }
    }

#pragma unroll
    for (int ii = 0; ii < 7; ii++) {
        const int i = r0 + ii;
        g_att[(size_t)(b * TOK + i) * KDIM + h * HDIM + lane] =
            __uint_as_float(f2tf(o[ii]));   // pre-rounded for proj GEMM
    }
}

// ---------------------------------------------------------------------------
extern "C" void kernel_launch(void* const* d_in, const int* in_sizes, int n_in,
                              void* d_out, int out_size)
{
    const float* x          = (const float*)d_in[0];
    const float* mask       = (const float*)d_in[1];
    const float* qkv_w      = (const float*)d_in[2];
    const float* qkv_b      = (const float*)d_in[3];
    const float* proj_w     = (const float*)d_in[4];
    const float* proj_b     = (const float*)d_in[5];
    const float* bias_table = (const float*)d_in[6];
    const int*   rel_index  = (const int*)d_in[7];
    float*       out        = (float*)d_out;

    // resolve REAL device addresses of __device__ globals (host shadow is invalid)
    float *p_xr, *p_wq, *p_wp, *p_att;
    cudaGetSymbolAddress((void**)&p_xr,  g_xr);
    cudaGetSymbolAddress((void**)&p_wq,  g_wq);
    cudaGetSymbolAddress((void**)&p_wp,  g_wp);
    cudaGetSymbolAddress((void**)&p_att, g_att);

    // tf32 (rna) pre-rounding
    round4<<<(MTOT * KDIM) / 4 / 256, 256>>>(x, p_xr);
    round4<<<(768 * KDIM) / 4 / 256, 256>>>(qkv_w, p_wq);
    round4<<<(KDIM * KDIM) / 4 / 256, 256>>>(proj_w, p_wp);

    bm_precompute<<<NMASK * NH, 256>>>(bias_table, rel_index, mask);

    dim3 g1(MTOT / 128, 768 / 128);
    gemm_tf32<0><<<g1, 256>>>(p_xr, p_wq, qkv_b, nullptr, 768);

    attn_kernel<<<NWIN * NH, 256>>>();

    dim3 g2(MTOT / 128, KDIM / 128);
    gemm_tf32<1><<<g2, 256>>>(p_att, p_wp, proj_b, out, KDIM);
}

// round 8
// speedup vs baseline: 1.6941x; 1.2577x over previous
#include <cuda_runtime.h>
#include <cuda_bf16.h>
#include <cstdint>

#define TOK 49
#define HDIM 32
#define NH 8
#define NWIN 4096
#define MTOT (NWIN * TOK)   /* 200704 */
#define KDIM 256
#define NMASK 64
#define BMROW 50            /* bm row stride (even -> aligned float2) */
#define BMSTRIDE 2452       /* per-(w,h) slice stride, >= 49*50, mult of 4 */

// ---------------- scratch (device globals: allocation-free) ----------------
__device__ float g_q[NWIN * NH * TOK * HDIM];   // [b,h,t,d]
__device__ float g_k[NWIN * NH * TOK * HDIM];
__device__ float g_v[NWIN * NH * TOK * HDIM];
__device__ float g_att[MTOT * KDIM];            // [b*49+t, h*32+d] (tf32-rounded)
__device__ float g_bm[NMASK * NH * BMSTRIDE];   // fused bias+mask per (w,h)
__device__ float g_xr[MTOT * KDIM];             // x, tf32-rounded
__device__ float g_wq[768 * KDIM];              // qkv_w, tf32-rounded
__device__ float g_wp[KDIM * KDIM];             // proj_w, tf32-rounded

__device__ __forceinline__ float4 ld4(const float* p) {
    return *reinterpret_cast<const float4*>(p);
}
__device__ __forceinline__ void st4(float* p, float4 v) {
    *reinterpret_cast<float4*>(p) = v;
}
__device__ __forceinline__ void st2(float* p, float2 v) {
    *reinterpret_cast<float2*>(p) = v;
}
__device__ __forceinline__ uint32_t f2tf(float f) {
    uint32_t u;
    asm("cvt.rna.tf32.f32 %0, %1;" : "=r"(u) : "f"(f));
    return u;
}
__device__ __forceinline__ float tfr(float f) { return __uint_as_float(f2tf(f)); }
__device__ __forceinline__ void cp16(float* smem_dst, const float* gmem_src) {
    uint32_t s = (uint32_t)__cvta_generic_to_shared(smem_dst);
    asm volatile("cp.async.cg.shared.global [%0], [%1], 16;" :: "r"(s), "l"(gmem_src));
}
__device__ __forceinline__ void mma_tf32(float c[4],
                                         uint32_t a0, uint32_t a1, uint32_t a2, uint32_t a3,
                                         uint32_t b0, uint32_t b1) {
    asm volatile(
        "mma.sync.aligned.m16n8k8.row.col.f32.tf32.tf32.f32 "
        "{%0,%1,%2,%3}, {%4,%5,%6,%7}, {%8,%9}, {%0,%1,%2,%3};"
        : "+f"(c[0]), "+f"(c[1]), "+f"(c[2]), "+f"(c[3])
        : "r"(a0), "r"(a1), "r"(a2), "r"(a3), "r"(b0), "r"(b1));
}

// ---------------------------------------------------------------------------
// elementwise tf32 (rna) pre-round
// ---------------------------------------------------------------------------
__global__ void round4(const float* __restrict__ in, float* __restrict__ out) {
    const size_t i = (size_t)(blockIdx.x * blockDim.x + threadIdx.x) * 4;
    float4 v = ld4(in + i);
    v.x = tfr(v.x); v.y = tfr(v.y); v.z = tfr(v.z); v.w = tfr(v.w);
    st4(out + i, v);
}

// ---------------------------------------------------------------------------
// tf32 tensor-core GEMM (NT). Grid: x = n-tiles (fast), y = m-tiles, so the
// n-tiles sharing an A tile are concurrent -> A read ~once from DRAM (L2 hits).
// Block 128x128, BK=16, 8 warps (2m x 4n), warp tile 64x32, cp.async dbuf.
// ---------------------------------------------------------------------------
#define RS 20   // smem row stride (floats)

template <int MODE>
__global__ __launch_bounds__(256, 2)
void gemm_tf32(const float* __restrict__ A, const float* __restrict__ B,
               const float* __restrict__ bias, float* __restrict__ C, int N)
{
    __shared__ float As[2][128 * RS];
    __shared__ float Bs[2][128 * RS];

    const int tid  = threadIdx.x;
    const int m0   = blockIdx.y * 128;
    const int n0   = blockIdx.x * 128;
    const int warp = tid >> 5;
    const int lane = tid & 31;
    const int g    = lane >> 2;
    const int tig  = lane & 3;
    const int wm   = warp & 1;
    const int wn   = warp >> 1;

    const int lr = tid >> 1;
    const int lc = (tid & 1) * 8;
    const float* Ag = A + (size_t)(m0 + lr) * KDIM + lc;
    const float* Bg = B + (size_t)(n0 + lr) * KDIM + lc;
    const int sdst = lr * RS + lc;

    float acc[4][4][4];
#pragma unroll
    for (int mi = 0; mi < 4; mi++)
#pragma unroll
        for (int ni = 0; ni < 4; ni++)
#pragma unroll
            for (int e = 0; e < 4; e++) acc[mi][ni][e] = 0.f;

    auto issue = [&](int s, int kt) {
        cp16(&As[s][sdst],     Ag + kt);
        cp16(&As[s][sdst + 4], Ag + kt + 4);
        cp16(&Bs[s][sdst],     Bg + kt);
        cp16(&Bs[s][sdst + 4], Bg + kt + 4);
        asm volatile("cp.async.commit_group;");
    };

    issue(0, 0);

    const int NT = KDIM / 16;
#pragma unroll 1
    for (int iter = 0; iter < NT; iter++) {
        asm volatile("cp.async.wait_group 0;");
        __syncthreads();
        if (iter + 1 < NT) issue((iter + 1) & 1, (iter + 1) * 16);

        const uint32_t* sA = reinterpret_cast<const uint32_t*>(As[iter & 1]);
        const uint32_t* sB = reinterpret_cast<const uint32_t*>(Bs[iter & 1]);
#pragma unroll
        for (int k8 = 0; k8 < 16; k8 += 8) {
            uint32_t a[4][4], bf[4][2];
#pragma unroll
            for (int mi = 0; mi < 4; mi++) {
                const int mg = (wm * 64 + mi * 16 + g) * RS;
                a[mi][0] = sA[mg + k8 + tig];
                a[mi][1] = sA[mg + 8 * RS + k8 + tig];
                a[mi][2] = sA[mg + k8 + tig + 4];
                a[mi][3] = sA[mg + 8 * RS + k8 + tig + 4];
            }
#pragma unroll
            for (int ni = 0; ni < 4; ni++) {
                const int ng = (wn * 32 + ni * 8 + g) * RS;
                bf[ni][0] = sB[ng + k8 + tig];
                bf[ni][1] = sB[ng + k8 + tig + 4];
            }
#pragma unroll
            for (int mi = 0; mi < 4; mi++)
#pragma unroll
                for (int ni = 0; ni < 4; ni++)
                    mma_tf32(acc[mi][ni], a[mi][0], a[mi][1], a[mi][2], a[mi][3],
                             bf[ni][0], bf[ni][1]);
        }
        __syncthreads();
    }

    if (MODE == 0) {
        const float SC = 0.17677669529663687f;
#pragma unroll
        for (int mi = 0; mi < 4; mi++) {
#pragma unroll
            for (int half = 0; half < 2; half++) {
                const int m  = m0 + wm * 64 + mi * 16 + g + half * 8;
                const int bw = m / TOK;
                const int t  = m - bw * TOK;
#pragma unroll
                for (int ni = 0; ni < 4; ni++) {
                    const int n     = n0 + wn * 32 + ni * 8 + 2 * tig;
                    const int which = n >> 8;
                    const int h     = (n >> 5) & 7;
                    const int d     = n & 31;
                    float2 v;
                    v.x = acc[mi][ni][half * 2 + 0] + bias[n + 0];
                    v.y = acc[mi][ni][half * 2 + 1] + bias[n + 1];
                    if (which == 0) { v.x *= SC; v.y *= SC; }
                    float* dst = (which == 0) ? g_q : (which == 1) ? g_k : g_v;
                    st2(&dst[(size_t)((bw * NH + h) * TOK + t) * HDIM + d], v);
                }
            }
        }
    } else {
#pragma unroll
        for (int mi = 0; mi < 4; mi++) {
#pragma unroll
            for (int half = 0; half < 2; half++) {
                const int m = m0 + wm * 64 + mi * 16 + g + half * 8;
#pragma unroll
                for (int ni = 0; ni < 4; ni++) {
                    const int n = n0 + wn * 32 + ni * 8 + 2 * tig;
                    float2 v;
                    v.x = acc[mi][ni][half * 2 + 0] + bias[n + 0];
                    v.y = acc[mi][ni][half * 2 + 1] + bias[n + 1];
                    st2(C + (size_t)m * N + n, v);
                }
            }
        }
    }
}

// ---------------------------------------------------------------------------
// Precompute fused bias+mask, row stride 50 (even -> aligned float2 reads)
// ---------------------------------------------------------------------------
__global__ void bm_precompute(const float* __restrict__ bias_table,
                              const int* __restrict__ rel_index,
                              const float* __restrict__ mask)
{
    const int w = blockIdx.x >> 3;
    float* dst = g_bm + (size_t)blockIdx.x * BMSTRIDE;
    const int h = blockIdx.x & 7;
    const float* mrow = mask + (size_t)w * (TOK * TOK);
    for (int e = threadIdx.x; e < TOK * TOK; e += 256) {
        const int i = e / TOK;
        const int j = e - i * TOK;
        dst[i * BMROW + j] = bias_table[rel_index[e] * NH + h] + mrow[e];
    }
}

// ---------------------------------------------------------------------------
// Tensor-core attention: one block (4 warps, 128 thr) per (b,h).
// Warp w owns 16 query rows (mrow = 16w). S = QK^T via 28 mma, in-register
// quad-shuffle softmax, P -> smem (aliases dead Q/K region), PV via 28 mma.
// ---------------------------------------------------------------------------
#define STQ 36   // Qs/Ks row stride
#define STV 60   // Vt / Ps row stride

__global__ __launch_bounds__(128)
void attn_mma()
{
    __shared__ float sm[6240];
    float* Qs = sm;            // 64 x STQ  (rows >=49 zero)
    float* Ks = sm + 2304;     // 56 x STQ  (rows >=49 zero)
    float* Vt = sm + 4320;     // 32 x STV  (cols = tokens, >=49 zero)
    float* Ps = sm;            // alias over Qs+Ks after S phase (64 x STV)

    const int tid  = threadIdx.x;
    const int warp = tid >> 5;
    const int lane = tid & 31;
    const int g    = lane >> 2;
    const int tig  = lane & 3;
    const int bh   = blockIdx.x;
    const int b    = bh >> 3;
    const int h    = bh & 7;
    const int base = bh * (TOK * HDIM);

    // ---- stage Q (64 rows), K + V-transposed (56 rows), all tf32-rounded ----
    for (int idx = tid; idx < 64 * 8; idx += 128) {
        const int r = idx >> 3;
        const int c = (idx & 7) * 4;
        float4 v = (r < TOK) ? ld4(g_q + base + r * HDIM + c)
                             : make_float4(0.f, 0.f, 0.f, 0.f);
        Qs[r * STQ + c + 0] = tfr(v.x);
        Qs[r * STQ + c + 1] = tfr(v.y);
        Qs[r * STQ + c + 2] = tfr(v.z);
        Qs[r * STQ + c + 3] = tfr(v.w);
    }
    for (int idx = tid; idx < 56 * 8; idx += 128) {
        const int r = idx >> 3;          // token
        const int c = (idx & 7) * 4;     // d base
        float4 kv, vv;
        if (r < TOK) {
            kv = ld4(g_k + base + r * HDIM + c);
            vv = ld4(g_v + base + r * HDIM + c);
        } else {
            kv = make_float4(0.f, 0.f, 0.f, 0.f);
            vv = kv;
        }
        Ks[r * STQ + c + 0] = tfr(kv.x);
        Ks[r * STQ + c + 1] = tfr(kv.y);
        Ks[r * STQ + c + 2] = tfr(kv.z);
        Ks[r * STQ + c + 3] = tfr(kv.w);
        Vt[(c + 0) * STV + r] = tfr(vv.x);
        Vt[(c + 1) * STV + r] = tfr(vv.y);
        Vt[(c + 2) * STV + r] = tfr(vv.z);
        Vt[(c + 3) * STV + r] = tfr(vv.w);
    }
    __syncthreads();

    const int mrow = warp * 16;
    const uint32_t* Qu = reinterpret_cast<const uint32_t*>(Qs);
    const uint32_t* Ku = reinterpret_cast<const uint32_t*>(Ks);
    const uint32_t* Vu = reinterpret_cast<const uint32_t*>(Vt);

    // ---- S = Q K^T ----
    float sacc[7][4];
#pragma unroll
    for (int j = 0; j < 7; j++)
#pragma unroll
        for (int e = 0; e < 4; e++) sacc[j][e] = 0.f;

#pragma unroll
    for (int kt = 0; kt < 4; kt++) {
        const int ko = kt * 8;
        uint32_t a0 = Qu[(mrow + g) * STQ + ko + tig];
        uint32_t a1 = Qu[(mrow + g + 8) * STQ + ko + tig];
        uint32_t a2 = Qu[(mrow + g) * STQ + ko + tig + 4];
        uint32_t a3 = Qu[(mrow + g + 8) * STQ + ko + tig + 4];
#pragma unroll
        for (int j = 0; j < 7; j++) {
            uint32_t b0 = Ku[(j * 8 + g) * STQ + ko + tig];
            uint32_t b1 = Ku[(j * 8 + g) * STQ + ko + tig + 4];
            mma_tf32(sacc[j], a0, a1, a2, a3, b0, b1);
        }
    }

    // ---- bias+mask + softmax (rows r1 = mrow+g, r2 = mrow+g+8) ----
    const int r1 = mrow + g;
    const int r2 = r1 + 8;
    const float* bmb = g_bm + (size_t)(((b & (NMASK - 1)) << 3) + h) * BMSTRIDE;
    const float* bm1 = bmb + (r1 < TOK ? r1 : 48) * BMROW;
    const float* bm2 = bmb + (r2 < TOK ? r2 : 48) * BMROW;

    float mx1 = -1e30f, mx2 = -1e30f;
#pragma unroll
    for (int j = 0; j < 7; j++) {
        const int cc = j * 8 + 2 * tig;
        const float2 bb1 = *reinterpret_cast<const float2*>(bm1 + cc);
        const float2 bb2 = *reinterpret_cast<const float2*>(bm2 + cc);
        sacc[j][0] = (cc     < TOK) ? sacc[j][0] + bb1.x : -1e30f;
        sacc[j][1] = (cc + 1 < TOK) ? sacc[j][1] + bb1.y : -1e30f;
        sacc[j][2] = (cc     < TOK) ? sacc[j][2] + bb2.x : -1e30f;
        sacc[j][3] = (cc + 1 < TOK) ? sacc[j][3] + bb2.y : -1e30f;
        mx1 = fmaxf(mx1, fmaxf(sacc[j][0], sacc[j][1]));
        mx2 = fmaxf(mx2, fmaxf(sacc[j][2], sacc[j][3]));
    }
    mx1 = fmaxf(mx1, __shfl_xor_sync(0xffffffffu, mx1, 1));
    mx1 = fmaxf(mx1, __shfl_xor_sync(0xffffffffu, mx1, 2));
    mx2 = fmaxf(mx2, __shfl_xor_sync(0xffffffffu, mx2, 1));
    mx2 = fmaxf(mx2, __shfl_xor_sync(0xffffffffu, mx2, 2));

    float s1 = 0.f, s2 = 0.f;
#pragma unroll
    for (int j = 0; j < 7; j++) {
        sacc[j][0] = __expf(sacc[j][0] - mx1);
        sacc[j][1] = __expf(sacc[j][1] - mx1);
        sacc[j][2] = __expf(sacc[j][2] - mx2);
        sacc[j][3] = __expf(sacc[j][3] - mx2);
        s1 += sacc[j][0] + sacc[j][1];
        s2 += sacc[j][2] + sacc[j][3];
    }
    s1 += __shfl_xor_sync(0xffffffffu, s1, 1);
    s1 += __shfl_xor_sync(0xffffffffu, s1, 2);
    s2 += __shfl_xor_sync(0xffffffffu, s2, 1);
    s2 += __shfl_xor_sync(0xffffffffu, s2, 2);
    const float inv1 = 1.f / s1;
    const float inv2 = 1.f / s2;

    // ---- P -> smem (aliases Qs/Ks; all warps must finish reading first) ----
    __syncthreads();
#pragma unroll
    for (int j = 0; j < 7; j++) {
        const int cc = j * 8 + 2 * tig;
        st2(&Ps[r1 * STV + cc], make_float2(tfr(sacc[j][0] * inv1), tfr(sacc[j][1] * inv1)));
        st2(&Ps[r2 * STV + cc], make_float2(tfr(sacc[j][2] * inv2), tfr(sacc[j][3] * inv2)));
    }
    __syncwarp();

    // ---- O = P @ V ----
    const uint32_t* Pu = reinterpret_cast<const uint32_t*>(Ps);
    float oacc[4][4];
#pragma unroll
    for (int nt = 0; nt < 4; nt++)
#pragma unroll
        for (int e = 0; e < 4; e++) oacc[nt][e] = 0.f;

#pragma unroll
    for (int kt = 0; kt < 7; kt++) {
        const int ko = kt * 8;
        uint32_t a0 = Pu[(mrow + g) * STV + ko + tig];
        uint32_t a1 = Pu[(mrow + g + 8) * STV + ko + tig];
        uint32_t a2 = Pu[(mrow + g) * STV + ko + tig + 4];
        uint32_t a3 = Pu[(mrow + g + 8) * STV + ko + tig + 4];
#pragma unroll
        for (int nt = 0; nt < 4; nt++) {
            uint32_t b0 = Vu[(nt * 8 + g) * STV + ko + tig];
            uint32_t b1 = Vu[(nt * 8 + g) * STV + ko + tig + 4];
            mma_tf32(oacc[nt], a0, a1, a2, a3, b0, b1);
        }
    }

    // ---- write O (tf32-rounded for the proj GEMM) ----
#pragma unroll
    for (int nt = 0; nt < 4; nt++) {
        const int d = nt * 8 + 2 * tig;
        if (r1 < TOK)
            st2(&g_att[(size_t)(b * TOK + r1) * KDIM + h * HDIM + d],
                make_float2(tfr(oacc[nt][0]), tfr(oacc[nt][1])));
        if (r2 < TOK)
            st2(&g_att[(size_t)(b * TOK + r2) * KDIM + h * HDIM + d],
                make_float2(tfr(oacc[nt][2]), tfr(oacc[nt][3])));
    }
}

// ---------------------------------------------------------------------------
extern "C" void kernel_launch(void* const* d_in, const int* in_sizes, int n_in,
                              void* d_out, int out_size)
{
    const float* x          = (const float*)d_in[0];
    const float* mask       = (const float*)d_in[1];
    const float* qkv_w      = (const float*)d_in[2];
    const float* qkv_b      = (const float*)d_in[3];
    const float* proj_w     = (const float*)d_in[4];
    const float* proj_b     = (const float*)d_in[5];
    const float* bias_table = (const float*)d_in[6];
    const int*   rel_index  = (const int*)d_in[7];
    float*       out        = (float*)d_out;

    float *p_xr, *p_wq, *p_wp, *p_att;
    cudaGetSymbolAddress((void**)&p_xr,  g_xr);
    cudaGetSymbolAddress((void**)&p_wq,  g_wq);
    cudaGetSymbolAddress((void**)&p_wp,  g_wp);
    cudaGetSymbolAddress((void**)&p_att, g_att);

    round4<<<(MTOT * KDIM) / 4 / 256, 256>>>(x, p_xr);
    round4<<<(768 * KDIM) / 4 / 256, 256>>>(qkv_w, p_wq);
    round4<<<(KDIM * KDIM) / 4 / 256, 256>>>(proj_w, p_wp);

    bm_precompute<<<NMASK * NH, 256>>>(bias_table, rel_index, mask);

    dim3 g1(768 / 128, MTOT / 128);             // x = n (fast) -> A reuse in L2
    gemm_tf32<0><<<g1, 256>>>(p_xr, p_wq, qkv_b, nullptr, 768);

    attn_mma<<<NWIN * NH, 128>>>();

    dim3 g2(KDIM / 128, MTOT / 128);
    gemm_tf32<1><<<g2, 256>>>(p_att, p_wp, proj_b, out, KDIM);
}

// round 9
// speedup vs baseline: 1.7535x; 1.0350x over previous
#include <cuda_runtime.h>
#include <cuda_bf16.h>
#include <cstdint>

#define TOK 49
#define HDIM 32
#define NH 8
#define NWIN 4096
#define MTOT (NWIN * TOK)   /* 200704 */
#define KDIM 256
#define NMASK 64
#define BMROW 50
#define BMSTRIDE 2452

// ---------------- scratch (device globals: allocation-free) ----------------
__device__ float g_q[NWIN * NH * TOK * HDIM];   // [b,h,t,d]
__device__ float g_k[NWIN * NH * TOK * HDIM];
__device__ float g_v[NWIN * NH * TOK * HDIM];
__device__ float g_att[MTOT * KDIM];            // [b*49+t, h*32+d] (tf32-rounded)
__device__ float g_bm[NMASK * NH * BMSTRIDE];   // fused bias+mask per (w,h)
__device__ float g_wq[768 * KDIM];              // qkv_w, tf32-rounded
__device__ float g_wp[KDIM * KDIM];             // proj_w, tf32-rounded

__device__ __forceinline__ float4 ld4(const float* p) {
    return *reinterpret_cast<const float4*>(p);
}
__device__ __forceinline__ void st4(float* p, float4 v) {
    *reinterpret_cast<float4*>(p) = v;
}
__device__ __forceinline__ void st2(float* p, float2 v) {
    *reinterpret_cast<float2*>(p) = v;
}
__device__ __forceinline__ uint32_t f2tf(float f) {
    uint32_t u;
    asm("cvt.rna.tf32.f32 %0, %1;" : "=r"(u) : "f"(f));
    return u;
}
__device__ __forceinline__ float tfr(float f) { return __uint_as_float(f2tf(f)); }
__device__ __forceinline__ void cp16(float* smem_dst, const float* gmem_src) {
    uint32_t s = (uint32_t)__cvta_generic_to_shared(smem_dst);
    asm volatile("cp.async.cg.shared.global [%0], [%1], 16;" :: "r"(s), "l"(gmem_src));
}
__device__ __forceinline__ void mma_tf32(float c[4],
                                         uint32_t a0, uint32_t a1, uint32_t a2, uint32_t a3,
                                         uint32_t b0, uint32_t b1) {
    asm volatile(
        "mma.sync.aligned.m16n8k8.row.col.f32.tf32.tf32.f32 "
        "{%0,%1,%2,%3}, {%4,%5,%6,%7}, {%8,%9}, {%0,%1,%2,%3};"
        : "+f"(c[0]), "+f"(c[1]), "+f"(c[2]), "+f"(c[3])
        : "r"(a0), "r"(a1), "r"(a2), "r"(a3), "r"(b0), "r"(b1));
}

// ---------------------------------------------------------------------------
// elementwise tf32 (rna) pre-round (weights only now)
// ---------------------------------------------------------------------------
__global__ void round4(const float* __restrict__ in, float* __restrict__ out) {
    const size_t i = (size_t)(blockIdx.x * blockDim.x + threadIdx.x) * 4;
    float4 v = ld4(in + i);
    v.x = tfr(v.x); v.y = tfr(v.y); v.z = tfr(v.z); v.w = tfr(v.w);
    st4(out + i, v);
}

// ---------------------------------------------------------------------------
// tf32 tensor-core GEMM (NT), 4-stage cp.async pipeline in dynamic smem.
// Block 128x128, BK=16, 8 warps (2m x 4n), warp tile 64x32.
// One __syncthreads per K-tile; wait_group 2 keeps 2 copies in flight.
// MODE 0: A = x raw fp32, fragments cvt'd to tf32 in-loop; scatter epilogue.
// MODE 1: A already tf32-rounded; plain epilogue.
// ---------------------------------------------------------------------------
#define RS 20          // smem row stride (floats)
#define STG 4          // pipeline stages
#define STGF (2 * 128 * RS)   // floats per stage (A then B)

extern __shared__ float smx[];

template <int MODE>
__global__ __launch_bounds__(256, 2)
void gemm_tf32(const float* __restrict__ A, const float* __restrict__ B,
               const float* __restrict__ bias, float* __restrict__ C, int N)
{
    const int tid  = threadIdx.x;
    const int m0   = blockIdx.y * 128;
    const int n0   = blockIdx.x * 128;
    const int warp = tid >> 5;
    const int lane = tid & 31;
    const int g    = lane >> 2;
    const int tig  = lane & 3;
    const int wm   = warp & 1;
    const int wn   = warp >> 1;

    const int lr = tid >> 1;
    const int lc = (tid & 1) * 8;
    const float* Ag = A + (size_t)(m0 + lr) * KDIM + lc;
    const float* Bg = B + (size_t)(n0 + lr) * KDIM + lc;
    const int sdst = lr * RS + lc;

    float acc[4][4][4];
#pragma unroll
    for (int mi = 0; mi < 4; mi++)
#pragma unroll
        for (int ni = 0; ni < 4; ni++)
#pragma unroll
            for (int e = 0; e < 4; e++) acc[mi][ni][e] = 0.f;

    auto issue = [&](int s, int kt) {
        float* As = smx + s * STGF;
        float* Bs = As + 128 * RS;
        cp16(&As[sdst],     Ag + kt);
        cp16(&As[sdst + 4], Ag + kt + 4);
        cp16(&Bs[sdst],     Bg + kt);
        cp16(&Bs[sdst + 4], Bg + kt + 4);
        asm volatile("cp.async.commit_group;");
    };

    const int NT = KDIM / 16;
    // prologue: stages 0..STG-2
#pragma unroll
    for (int s = 0; s < STG - 1; s++) issue(s, s * 16);

#pragma unroll 1
    for (int iter = 0; iter < NT; iter++) {
        asm volatile("cp.async.wait_group %0;" :: "n"(STG - 2));
        __syncthreads();
        // keep exactly one commit per iteration (empty near the tail)
        if (iter + STG - 1 < NT) issue((iter + STG - 1) % STG, (iter + STG - 1) * 16);
        else asm volatile("cp.async.commit_group;");

        const int st = iter % STG;
        const uint32_t* sA = reinterpret_cast<const uint32_t*>(smx + st * STGF);
        const uint32_t* sB = sA + 128 * RS;
#pragma unroll
        for (int k8 = 0; k8 < 16; k8 += 8) {
            uint32_t a[4][4], bf[4][2];
#pragma unroll
            for (int mi = 0; mi < 4; mi++) {
                const int mg = (wm * 64 + mi * 16 + g) * RS;
                a[mi][0] = sA[mg + k8 + tig];
                a[mi][1] = sA[mg + 8 * RS + k8 + tig];
                a[mi][2] = sA[mg + k8 + tig + 4];
                a[mi][3] = sA[mg + 8 * RS + k8 + tig + 4];
                if (MODE == 0) {
#pragma unroll
                    for (int e = 0; e < 4; e++)
                        a[mi][e] = f2tf(__uint_as_float(a[mi][e]));
                }
            }
#pragma unroll
            for (int ni = 0; ni < 4; ni++) {
                const int ng = (wn * 32 + ni * 8 + g) * RS;
                bf[ni][0] = sB[ng + k8 + tig];
                bf[ni][1] = sB[ng + k8 + tig + 4];
            }
#pragma unroll
            for (int mi = 0; mi < 4; mi++)
#pragma unroll
                for (int ni = 0; ni < 4; ni++)
                    mma_tf32(acc[mi][ni], a[mi][0], a[mi][1], a[mi][2], a[mi][3],
                             bf[ni][0], bf[ni][1]);
        }
    }

    if (MODE == 0) {
        const float SC = 0.17677669529663687f;
#pragma unroll
        for (int mi = 0; mi < 4; mi++) {
#pragma unroll
            for (int half = 0; half < 2; half++) {
                const int m  = m0 + wm * 64 + mi * 16 + g + half * 8;
                const int bw = m / TOK;
                const int t  = m - bw * TOK;
#pragma unroll
                for (int ni = 0; ni < 4; ni++) {
                    const int n     = n0 + wn * 32 + ni * 8 + 2 * tig;
                    const int which = n >> 8;
                    const int h     = (n >> 5) & 7;
                    const int d     = n & 31;
                    float2 v;
                    v.x = acc[mi][ni][half * 2 + 0] + bias[n + 0];
                    v.y = acc[mi][ni][half * 2 + 1] + bias[n + 1];
                    if (which == 0) { v.x *= SC; v.y *= SC; }
                    float* dst = (which == 0) ? g_q : (which == 1) ? g_k : g_v;
                    st2(&dst[(size_t)((bw * NH + h) * TOK + t) * HDIM + d], v);
                }
            }
        }
    } else {
#pragma unroll
        for (int mi = 0; mi < 4; mi++) {
#pragma unroll
            for (int half = 0; half < 2; half++) {
                const int m = m0 + wm * 64 + mi * 16 + g + half * 8;
#pragma unroll
                for (int ni = 0; ni < 4; ni++) {
                    const int n = n0 + wn * 32 + ni * 8 + 2 * tig;
                    float2 v;
                    v.x = acc[mi][ni][half * 2 + 0] + bias[n + 0];
                    v.y = acc[mi][ni][half * 2 + 1] + bias[n + 1];
                    st2(C + (size_t)m * N + n, v);
                }
            }
        }
    }
}

// ---------------------------------------------------------------------------
// Precompute fused bias+mask (row stride 50)
// ---------------------------------------------------------------------------
__global__ void bm_precompute(const float* __restrict__ bias_table,
                              const int* __restrict__ rel_index,
                              const float* __restrict__ mask)
{
    const int w = blockIdx.x >> 3;
    float* dst = g_bm + (size_t)blockIdx.x * BMSTRIDE;
    const int h = blockIdx.x & 7;
    const float* mrow = mask + (size_t)w * (TOK * TOK);
    for (int e = threadIdx.x; e < TOK * TOK; e += 256) {
        const int i = e / TOK;
        const int j = e - i * TOK;
        dst[i * BMROW + j] = bias_table[rel_index[e] * NH + h] + mrow[e];
    }
}

// ---------------------------------------------------------------------------
// Tensor-core attention (unchanged from round 8 — known good)
// ---------------------------------------------------------------------------
#define STQ 36
#define STV 60

__global__ __launch_bounds__(128)
void attn_mma()
{
    __shared__ float sm[6240];
    float* Qs = sm;
    float* Ks = sm + 2304;
    float* Vt = sm + 4320;
    float* Ps = sm;

    const int tid  = threadIdx.x;
    const int warp = tid >> 5;
    const int lane = tid & 31;
    const int g    = lane >> 2;
    const int tig  = lane & 3;
    const int bh   = blockIdx.x;
    const int b    = bh >> 3;
    const int h    = bh & 7;
    const int base = bh * (TOK * HDIM);

    for (int idx = tid; idx < 64 * 8; idx += 128) {
        const int r = idx >> 3;
        const int c = (idx & 7) * 4;
        float4 v = (r < TOK) ? ld4(g_q + base + r * HDIM + c)
                             : make_float4(0.f, 0.f, 0.f, 0.f);
        Qs[r * STQ + c + 0] = tfr(v.x);
        Qs[r * STQ + c + 1] = tfr(v.y);
        Qs[r * STQ + c + 2] = tfr(v.z);
        Qs[r * STQ + c + 3] = tfr(v.w);
    }
    for (int idx = tid; idx < 56 * 8; idx += 128) {
        const int r = idx >> 3;
        const int c = (idx & 7) * 4;
        float4 kv, vv;
        if (r < TOK) {
            kv = ld4(g_k + base + r * HDIM + c);
            vv = ld4(g_v + base + r * HDIM + c);
        } else {
            kv = make_float4(0.f, 0.f, 0.f, 0.f);
            vv = kv;
        }
        Ks[r * STQ + c + 0] = tfr(kv.x);
        Ks[r * STQ + c + 1] = tfr(kv.y);
        Ks[r * STQ + c + 2] = tfr(kv.z);
        Ks[r * STQ + c + 3] = tfr(kv.w);
        Vt[(c + 0) * STV + r] = tfr(vv.x);
        Vt[(c + 1) * STV + r] = tfr(vv.y);
        Vt[(c + 2) * STV + r] = tfr(vv.z);
        Vt[(c + 3) * STV + r] = tfr(vv.w);
    }
    __syncthreads();

    const int mrow = warp * 16;
    const uint32_t* Qu = reinterpret_cast<const uint32_t*>(Qs);
    const uint32_t* Ku = reinterpret_cast<const uint32_t*>(Ks);
    const uint32_t* Vu = reinterpret_cast<const uint32_t*>(Vt);

    float sacc[7][4];
#pragma unroll
    for (int j = 0; j < 7; j++)
#pragma unroll
        for (int e = 0; e < 4; e++) sacc[j][e] = 0.f;

#pragma unroll
    for (int kt = 0; kt < 4; kt++) {
        const int ko = kt * 8;
        uint32_t a0 = Qu[(mrow + g) * STQ + ko + tig];
        uint32_t a1 = Qu[(mrow + g + 8) * STQ + ko + tig];
        uint32_t a2 = Qu[(mrow + g) * STQ + ko + tig + 4];
        uint32_t a3 = Qu[(mrow + g + 8) * STQ + ko + tig + 4];
#pragma unroll
        for (int j = 0; j < 7; j++) {
            uint32_t b0 = Ku[(j * 8 + g) * STQ + ko + tig];
            uint32_t b1 = Ku[(j * 8 + g) * STQ + ko + tig + 4];
            mma_tf32(sacc[j], a0, a1, a2, a3, b0, b1);
        }
    }

    const int r1 = mrow + g;
    const int r2 = r1 + 8;
    const float* bmb = g_bm + (size_t)(((b & (NMASK - 1)) << 3) + h) * BMSTRIDE;
    const float* bm1 = bmb + (r1 < TOK ? r1 : 48) * BMROW;
    const float* bm2 = bmb + (r2 < TOK ? r2 : 48) * BMROW;

    float mx1 = -1e30f, mx2 = -1e30f;
#pragma unroll
    for (int j = 0; j < 7; j++) {
        const int cc = j * 8 + 2 * tig;
        const float2 bb1 = *reinterpret_cast<const float2*>(bm1 + cc);
        const float2 bb2 = *reinterpret_cast<const float2*>(bm2 + cc);
        sacc[j][0] = (cc     < TOK) ? sacc[j][0] + bb1.x : -1e30f;
        sacc[j][1] = (cc + 1 < TOK) ? sacc[j][1] + bb1.y : -1e30f;
        sacc[j][2] = (cc     < TOK) ? sacc[j][2] + bb2.x : -1e30f;
        sacc[j][3] = (cc + 1 < TOK) ? sacc[j][3] + bb2.y : -1e30f;
        mx1 = fmaxf(mx1, fmaxf(sacc[j][0], sacc[j][1]));
        mx2 = fmaxf(mx2, fmaxf(sacc[j][2], sacc[j][3]));
    }
    mx1 = fmaxf(mx1, __shfl_xor_sync(0xffffffffu, mx1, 1));
    mx1 = fmaxf(mx1, __shfl_xor_sync(0xffffffffu, mx1, 2));
    mx2 = fmaxf(mx2, __shfl_xor_sync(0xffffffffu, mx2, 1));
    mx2 = fmaxf(mx2, __shfl_xor_sync(0xffffffffu, mx2, 2));

    float s1 = 0.f, s2 = 0.f;
#pragma unroll
    for (int j = 0; j < 7; j++) {
        sacc[j][0] = __expf(sacc[j][0] - mx1);
        sacc[j][1] = __expf(sacc[j][1] - mx1);
        sacc[j][2] = __expf(sacc[j][2] - mx2);
        sacc[j][3] = __expf(sacc[j][3] - mx2);
        s1 += sacc[j][0] + sacc[j][1];
        s2 += sacc[j][2] + sacc[j][3];
    }
    s1 += __shfl_xor_sync(0xffffffffu, s1, 1);
    s1 += __shfl_xor_sync(0xffffffffu, s1, 2);
    s2 += __shfl_xor_sync(0xffffffffu, s2, 1);
    s2 += __shfl_xor_sync(0xffffffffu, s2, 2);
    const float inv1 = 1.f / s1;
    const float inv2 = 1.f / s2;

    __syncthreads();
#pragma unroll
    for (int j = 0; j < 7; j++) {
        const int cc = j * 8 + 2 * tig;
        st2(&Ps[r1 * STV + cc], make_float2(tfr(sacc[j][0] * inv1), tfr(sacc[j][1] * inv1)));
        st2(&Ps[r2 * STV + cc], make_float2(tfr(sacc[j][2] * inv2), tfr(sacc[j][3] * inv2)));
    }
    __syncwarp();

    const uint32_t* Pu = reinterpret_cast<const uint32_t*>(Ps);
    float oacc[4][4];
#pragma unroll
    for (int nt = 0; nt < 4; nt++)
#pragma unroll
        for (int e = 0; e < 4; e++) oacc[nt][e] = 0.f;

#pragma unroll
    for (int kt = 0; kt < 7; kt++) {
        const int ko = kt * 8;
        uint32_t a0 = Pu[(mrow + g) * STV + ko + tig];
        uint32_t a1 = Pu[(mrow + g + 8) * STV + ko + tig];
        uint32_t a2 = Pu[(mrow + g) * STV + ko + tig + 4];
        uint32_t a3 = Pu[(mrow + g + 8) * STV + ko + tig + 4];
#pragma unroll
        for (int nt = 0; nt < 4; nt++) {
            uint32_t b0 = Vu[(nt * 8 + g) * STV + ko + tig];
            uint32_t b1 = Vu[(nt * 8 + g) * STV + ko + tig + 4];
            mma_tf32(oacc[nt], a0, a1, a2, a3, b0, b1);
        }
    }

#pragma unroll
    for (int nt = 0; nt < 4; nt++) {
        const int d = nt * 8 + 2 * tig;
        if (r1 < TOK)
            st2(&g_att[(size_t)(b * TOK + r1) * KDIM + h * HDIM + d],
                make_float2(tfr(oacc[nt][0]), tfr(oacc[nt][1])));
        if (r2 < TOK)
            st2(&g_att[(size_t)(b * TOK + r2) * KDIM + h * HDIM + d],
                make_float2(tfr(oacc[nt][2]), tfr(oacc[nt][3])));
    }
}

// ---------------------------------------------------------------------------
extern "C" void kernel_launch(void* const* d_in, const int* in_sizes, int n_in,
                              void* d_out, int out_size)
{
    const float* x          = (const float*)d_in[0];
    const float* mask       = (const float*)d_in[1];
    const float* qkv_w      = (const float*)d_in[2];
    const float* qkv_b      = (const float*)d_in[3];
    const float* proj_w     = (const float*)d_in[4];
    const float* proj_b     = (const float*)d_in[5];
    const float* bias_table = (const float*)d_in[6];
    const int*   rel_index  = (const int*)d_in[7];
    float*       out        = (float*)d_out;

    float *p_wq, *p_wp, *p_att;
    cudaGetSymbolAddress((void**)&p_wq,  g_wq);
    cudaGetSymbolAddress((void**)&p_wp,  g_wp);
    cudaGetSymbolAddress((void**)&p_att, g_att);

    const int smbytes = STG * STGF * 4;   // 81920 B
    cudaFuncSetAttribute(gemm_tf32<0>, cudaFuncAttributeMaxDynamicSharedMemorySize, smbytes);
    cudaFuncSetAttribute(gemm_tf32<1>, cudaFuncAttributeMaxDynamicSharedMemorySize, smbytes);

    // weights tf32 (rna) pre-round; x is rounded in-GEMM
    round4<<<(768 * KDIM) / 4 / 256, 256>>>(qkv_w, p_wq);
    round4<<<(KDIM * KDIM) / 4 / 256, 256>>>(proj_w, p_wp);

    bm_precompute<<<NMASK * NH, 256>>>(bias_table, rel_index, mask);

    dim3 g1(768 / 128, MTOT / 128);
    gemm_tf32<0><<<g1, 256, smbytes>>>(x, p_wq, qkv_b, nullptr, 768);

    attn_mma<<<NWIN * NH, 128>>>();

    dim3 g2(KDIM / 128, MTOT / 128);
    gemm_tf32<1><<<g2, 256, smbytes>>>(p_att, p_wp, proj_b, out, KDIM);
}